// round 11
// baseline (speedup 1.0000x reference)
#include <cuda_runtime.h>
#include <cuda_bf16.h>
#include <cuda_fp16.h>
#include <math.h>
#include <stdint.h>

// ---------------------------------------------------------------------------
// Mamba forward, L=2048, 4 layers.
// Layer GEMMs: fused fp16 hi/lo 2-pass HMMA (B-fragment reuse, 2-stage cp.async).
// LM head: single-pass fp16 HMMA (3-stage cp.async).
// Small GEMMs + scan (gate fused) + elementwise in fp32 SIMT.
// ---------------------------------------------------------------------------

#define LSEQ    2048
#define NEMBD   1024
#define DINNER  2048
#define DSTATE  16
#define DTRANK  64
#define DCONV   4
#define NVOCAB  50257
#define NLAYERS 4
#define XDBL_W  (DTRANK + 2 * DSTATE)   // 96

// ----------------------------- scratch (static) ----------------------------
__device__ __align__(16) float g_x    [LSEQ * NEMBD];
__device__ __align__(16) float g_xr   [LSEQ * 2 * DINNER];
__device__ __align__(16) float g_u    [LSEQ * DINNER];
__device__ __align__(16) float g_xdbl [LSEQ * XDBL_W];
__device__ __align__(16) float g_delta[LSEQ * DINNER];
__device__ __align__(16) float g_part [8 * LSEQ * XDBL_W];

__device__ __align__(16) __half g_hh [LSEQ * NEMBD];    // activations hi
__device__ __align__(16) __half g_hl [LSEQ * NEMBD];    // activations lo
__device__ __align__(16) __half g_yh [LSEQ * DINNER];
__device__ __align__(16) __half g_yl [LSEQ * DINNER];
__device__ __align__(16) __half g_wi [NLAYERS * 2 * DINNER * NEMBD];
__device__ __align__(16) __half g_wo [NLAYERS * NEMBD * DINNER];
__device__ __align__(16) __half g_embh[(size_t)NVOCAB * NEMBD];

// ----------------------------- MMA helpers ---------------------------------
__device__ __forceinline__ void ldm_x4(uint32_t* r, uint32_t a) {
    asm volatile("ldmatrix.sync.aligned.m8n8.x4.shared.b16 {%0,%1,%2,%3}, [%4];"
                 : "=r"(r[0]), "=r"(r[1]), "=r"(r[2]), "=r"(r[3]) : "r"(a));
}
__device__ __forceinline__ void mma_16816(float* c, const uint32_t* a, const uint32_t* b) {
    asm volatile("mma.sync.aligned.m16n8k16.row.col.f32.f16.f16.f32 "
        "{%0,%1,%2,%3}, {%4,%5,%6,%7}, {%8,%9}, {%0,%1,%2,%3};"
        : "+f"(c[0]), "+f"(c[1]), "+f"(c[2]), "+f"(c[3])
        : "r"(a[0]), "r"(a[1]), "r"(a[2]), "r"(a[3]), "r"(b[0]), "r"(b[1]));
}

#define CPASYNC16(dst, src, sz) \
    asm volatile("cp.async.cg.shared.global [%0], [%1], 16, %2;" \
                 :: "r"(dst), "l"(src), "r"(sz))

#define PITCH 72
#define TSTR  (128 * PITCH)
#define SMEM_G (6 * TSTR * 2)   // 110592 B (both tc kernels)

// ---------- fused hi/lo HMMA NT GEMM: C (+)= AH*B^T + AL*B^T ---------------
// CTA 128x128, BK=64, 2-stage cp.async, tiles {AH,AL,B}, 8 warps 64x32,
// 2 CTAs/SM. B fragment registers reused across hi/lo passes.
template <bool ACC>
__global__ __launch_bounds__(256, 2) void gemm_fused(
    const uint16_t* __restrict__ AH, const uint16_t* __restrict__ AL,
    const uint16_t* __restrict__ B,
    float* __restrict__ C, int N, int K, int ldc) {
    extern __shared__ __align__(16) uint16_t sm[];
    const int tid = threadIdx.x, lane = tid & 31, wid = tid >> 5;
    const int bm = blockIdx.x * 128, bn = blockIdx.y * 128;
    const int NC = K >> 6;
    const uint32_t smBase = (uint32_t)__cvta_generic_to_shared(sm);
    const int lrow = tid >> 3, lch = tid & 7;

    const int arow = (lane & 7) + ((lane >> 3) & 1) * 8;
    const int akc  = lane >> 4;
    const int brow = (lane & 7) + ((lane >> 4) << 3);
    const int bkc  = (lane >> 3) & 1;
    const int wm = (wid & 1) * 64;
    const int wn = (wid >> 1) * 32;

    float acc[4][4][4];
    #pragma unroll
    for (int i = 0; i < 4; i++)
        #pragma unroll
        for (int j = 0; j < 4; j++)
            #pragma unroll
            for (int k = 0; k < 4; k++) acc[i][j][k] = 0.f;

#define FISSUE(st, c) do { \
    int _k = (c); \
    _Pragma("unroll") \
    for (int _it = 0; _it < 4; _it++) { \
        int _r = lrow + _it * 32; \
        size_t _go = (size_t)(bm + _r) * K + _k * 64 + lch * 8; \
        uint32_t _so = 2u * ((st) * TSTR + _r * PITCH + lch * 8); \
        CPASYNC16(smBase + _so, AH + _go, 16); \
        CPASYNC16(smBase + 2u * (2 * TSTR) + _so, AL + _go, 16); \
        int _gr = bn + _r; \
        const uint16_t* _gb = B + (size_t)((_gr < N) ? _gr : 0) * K + _k * 64 + lch * 8; \
        CPASYNC16(smBase + 2u * (4 * TSTR) + _so, _gb, (_gr < N) ? 16 : 0); \
    } \
  } while (0)

#define FCOMPUTE(st) do { \
    uint32_t _hb = smBase + 2u * ((st) * TSTR); \
    uint32_t _lb = smBase + 2u * ((2 + (st)) * TSTR); \
    uint32_t _bb = smBase + 2u * ((4 + (st)) * TSTR); \
    _Pragma("unroll") \
    for (int kk = 0; kk < 4; kk++) { \
        uint32_t af[4][4], bf[2][4]; \
        _Pragma("unroll") \
        for (int nb = 0; nb < 2; nb++) \
            ldm_x4(bf[nb], _bb + 2u * ((wn + nb * 16 + brow) * PITCH + (kk * 2 + bkc) * 8)); \
        _Pragma("unroll") \
        for (int mi = 0; mi < 4; mi++) \
            ldm_x4(af[mi], _hb + 2u * ((wm + mi * 16 + arow) * PITCH + (kk * 2 + akc) * 8)); \
        _Pragma("unroll") \
        for (int mi = 0; mi < 4; mi++) \
            _Pragma("unroll") \
            for (int ni = 0; ni < 4; ni++) \
                mma_16816(acc[mi][ni], af[mi], &bf[ni >> 1][(ni & 1) * 2]); \
        _Pragma("unroll") \
        for (int mi = 0; mi < 4; mi++) \
            ldm_x4(af[mi], _lb + 2u * ((wm + mi * 16 + arow) * PITCH + (kk * 2 + akc) * 8)); \
        _Pragma("unroll") \
        for (int mi = 0; mi < 4; mi++) \
            _Pragma("unroll") \
            for (int ni = 0; ni < 4; ni++) \
                mma_16816(acc[mi][ni], af[mi], &bf[ni >> 1][(ni & 1) * 2]); \
    } \
  } while (0)

    FISSUE(0, 0);
    asm volatile("cp.async.commit_group;" ::: "memory");
    if (NC > 1) {
        FISSUE(1, 1);
        asm volatile("cp.async.commit_group;" ::: "memory");
    }
    for (int c = 0; c < NC; c++) {
        if (c + 1 < NC)
            asm volatile("cp.async.wait_group 1;" ::: "memory");
        else
            asm volatile("cp.async.wait_group 0;" ::: "memory");
        __syncthreads();
        FCOMPUTE(c & 1);
        if (c + 2 < NC) {
            __syncthreads();   // all warps done reading buf c&1 before overwrite
            FISSUE((c + 2) & 1, c + 2);
            asm volatile("cp.async.commit_group;" ::: "memory");
        }
    }
#undef FISSUE
#undef FCOMPUTE

    const int gid = lane >> 2, q2 = (lane & 3) * 2;
    #pragma unroll
    for (int mi = 0; mi < 4; mi++) {
        const size_t row0 = (size_t)(bm + wm + mi * 16 + gid);
        const size_t row1 = row0 + 8;
        #pragma unroll
        for (int ni = 0; ni < 4; ni++) {
            const int col = bn + wn + ni * 8 + q2;
            const float* cf = acc[mi][ni];
            if (col < N) {
                if (ACC) { C[row0 * ldc + col] += cf[0]; C[row1 * ldc + col] += cf[2]; }
                else     { C[row0 * ldc + col]  = cf[0]; C[row1 * ldc + col]  = cf[2]; }
            }
            if (col + 1 < N) {
                if (ACC) { C[row0 * ldc + col + 1] += cf[1]; C[row1 * ldc + col + 1] += cf[3]; }
                else     { C[row0 * ldc + col + 1]  = cf[1]; C[row1 * ldc + col + 1]  = cf[3]; }
            }
        }
    }
}

// ------------- single-pass HMMA NT GEMM (lm head), 3-stage -----------------
__global__ __launch_bounds__(256, 2) void gemm_mma4(
    const uint16_t* __restrict__ A0, const uint16_t* __restrict__ B,
    float* __restrict__ C, int N, int K, int ldc) {
    extern __shared__ __align__(16) uint16_t sm[];
    const int tid = threadIdx.x, lane = tid & 31, wid = tid >> 5;
    const int bm = blockIdx.x * 128, bn = blockIdx.y * 128;
    const int NC = K >> 6;
    const uint32_t smBase = (uint32_t)__cvta_generic_to_shared(sm);
    const int lrow = tid >> 3, lch = tid & 7;

    const int arow = (lane & 7) + ((lane >> 3) & 1) * 8;
    const int akc  = lane >> 4;
    const int brow = (lane & 7) + ((lane >> 4) << 3);
    const int bkc  = (lane >> 3) & 1;
    const int wm = (wid & 1) * 64;
    const int wn = (wid >> 1) * 32;

    float acc[4][4][4];
    #pragma unroll
    for (int i = 0; i < 4; i++)
        #pragma unroll
        for (int j = 0; j < 4; j++)
            #pragma unroll
            for (int k = 0; k < 4; k++) acc[i][j][k] = 0.f;

#define ISSUE(st, c) do { \
    int _k = (c); \
    _Pragma("unroll") \
    for (int _it = 0; _it < 4; _it++) { \
        int _r = lrow + _it * 32; \
        const uint16_t* _ga = A0 + (size_t)(bm + _r) * K + _k * 64 + lch * 8; \
        uint32_t _da = smBase + 2u * ((st) * TSTR + _r * PITCH + lch * 8); \
        CPASYNC16(_da, _ga, 16); \
        int _gr = bn + _r; \
        const uint16_t* _gb = B + (size_t)((_gr < N) ? _gr : 0) * K + _k * 64 + lch * 8; \
        uint32_t _db = smBase + 2u * (3 * TSTR + (st) * TSTR + _r * PITCH + lch * 8); \
        CPASYNC16(_db, _gb, (_gr < N) ? 16 : 0); \
    } \
  } while (0)

#define COMPUTE(st) do { \
    uint32_t _ab = smBase + 2u * ((st) * TSTR); \
    uint32_t _bb = smBase + 2u * (3 * TSTR + (st) * TSTR); \
    _Pragma("unroll") \
    for (int kk = 0; kk < 4; kk++) { \
        uint32_t af[4][4], bf[2][4]; \
        _Pragma("unroll") \
        for (int mi = 0; mi < 4; mi++) \
            ldm_x4(af[mi], _ab + 2u * ((wm + mi * 16 + arow) * PITCH + (kk * 2 + akc) * 8)); \
        _Pragma("unroll") \
        for (int nb = 0; nb < 2; nb++) \
            ldm_x4(bf[nb], _bb + 2u * ((wn + nb * 16 + brow) * PITCH + (kk * 2 + bkc) * 8)); \
        _Pragma("unroll") \
        for (int mi = 0; mi < 4; mi++) \
            _Pragma("unroll") \
            for (int ni = 0; ni < 4; ni++) \
                mma_16816(acc[mi][ni], af[mi], &bf[ni >> 1][(ni & 1) * 2]); \
    } \
  } while (0)

    ISSUE(0, 0);
    asm volatile("cp.async.commit_group;" ::: "memory");
    ISSUE(1, 1);
    asm volatile("cp.async.commit_group;" ::: "memory");

    for (int c = 0; c < NC; c++) {
        asm volatile("cp.async.wait_group 1;" ::: "memory");
        __syncthreads();
        if (c + 2 < NC) ISSUE((c + 2) % 3, c + 2);
        asm volatile("cp.async.commit_group;" ::: "memory");
        COMPUTE(c % 3);
    }
#undef ISSUE
#undef COMPUTE

    const int gid = lane >> 2, q2 = (lane & 3) * 2;
    #pragma unroll
    for (int mi = 0; mi < 4; mi++) {
        const size_t row0 = (size_t)(bm + wm + mi * 16 + gid);
        const size_t row1 = row0 + 8;
        #pragma unroll
        for (int ni = 0; ni < 4; ni++) {
            const int col = bn + wn + ni * 8 + q2;
            const float* cf = acc[mi][ni];
            if (col < N) {
                C[row0 * ldc + col] = cf[0];
                C[row1 * ldc + col] = cf[2];
            }
            if (col + 1 < N) {
                C[row0 * ldc + col + 1] = cf[1];
                C[row1 * ldc + col + 1] = cf[3];
            }
        }
    }
}

// ----------------------------- small helpers -------------------------------
__device__ __forceinline__ float sigm(float x) { return 1.0f / (1.0f + expf(-x)); }
__device__ __forceinline__ uint32_t packh2(float a, float b) {
    return (uint32_t)__half_as_ushort(__float2half_rn(a)) |
           ((uint32_t)__half_as_ushort(__float2half_rn(b)) << 16);
}
__device__ __forceinline__ void split2h(float a, float b, uint32_t& hi, uint32_t& lo) {
    __half ha = __float2half_rn(a), hb = __float2half_rn(b);
    float la = a - __half2float(ha), lb = b - __half2float(hb);
    hi = (uint32_t)__half_as_ushort(ha) | ((uint32_t)__half_as_ushort(hb) << 16);
    lo = packh2(la, lb);
}

// ----------------------------- conversions ---------------------------------
__global__ void convert_half_kernel(const float* __restrict__ src,
                                    __half* __restrict__ dst, int n4) {
    int i = blockIdx.x * blockDim.x + threadIdx.x;
    if (i >= n4) return;
    float4 v = reinterpret_cast<const float4*>(src)[i];
    uint2 o;
    o.x = packh2(v.x, v.y);
    o.y = packh2(v.z, v.w);
    reinterpret_cast<uint2*>(dst)[i] = o;
}

// ----------------------------- embedding gather ----------------------------
__global__ void embed_kernel(const int* __restrict__ tokens,
                             const float* __restrict__ emb,
                             float* __restrict__ x) {
    int l = blockIdx.x;
    int tok = tokens[l];
    const float4* src = reinterpret_cast<const float4*>(emb + (size_t)tok * NEMBD);
    float4* dst = reinterpret_cast<float4*>(x + (size_t)l * NEMBD);
    dst[threadIdx.x] = src[threadIdx.x];
}

// ---------------- rmsnorm (width 1024) with fp16 outputs -------------------
template <int OUT_MODE>   // 0: fp16 hi/lo; 1: fp16 single
__global__ void rmsnorm_out_kernel(const float* __restrict__ x,
                                   const float* __restrict__ w,
                                   const float* __restrict__ b,
                                   void* __restrict__ out_hi,
                                   void* __restrict__ out_lo) {
    int l = blockIdx.x;
    const float4* xr = reinterpret_cast<const float4*>(x + (size_t)l * NEMBD);
    float4 v = xr[threadIdx.x];
    float ss = v.x * v.x + v.y * v.y + v.z * v.z + v.w * v.w;
    #pragma unroll
    for (int o = 16; o > 0; o >>= 1) ss += __shfl_xor_sync(0xffffffffu, ss, o);
    __shared__ float wsum[8];
    __shared__ float inv_s;
    if ((threadIdx.x & 31) == 0) wsum[threadIdx.x >> 5] = ss;
    __syncthreads();
    if (threadIdx.x == 0) {
        float t = 0.f;
        #pragma unroll
        for (int k = 0; k < 8; k++) t += wsum[k];
        inv_s = rsqrtf(t / (float)NEMBD + 1e-6f);
    }
    __syncthreads();
    float inv = inv_s;
    float4 wv = reinterpret_cast<const float4*>(w)[threadIdx.x];
    float4 bv = reinterpret_cast<const float4*>(b)[threadIdx.x];
    float o0 = v.x * inv * wv.x + bv.x;
    float o1 = v.y * inv * wv.y + bv.y;
    float o2 = v.z * inv * wv.z + bv.z;
    float o3 = v.w * inv * wv.w + bv.w;
    size_t base = (size_t)l * NEMBD / 4 + threadIdx.x;
    if (OUT_MODE == 0) {
        uint2 h, lo;
        split2h(o0, o1, h.x, lo.x);
        split2h(o2, o3, h.y, lo.y);
        reinterpret_cast<uint2*>(out_hi)[base] = h;
        reinterpret_cast<uint2*>(out_lo)[base] = lo;
    } else {
        uint2 o;
        o.x = packh2(o0, o1);
        o.y = packh2(o2, o3);
        reinterpret_cast<uint2*>(out_hi)[base] = o;
    }
}

// ------------------- fp32 tiled NT GEMM (small GEMMs) ----------------------
template <bool ACC, bool SPLIT, bool SOFTP>
__global__ __launch_bounds__(256) void gemm_nt(
    const float* __restrict__ A, const float* __restrict__ B,
    float* __restrict__ C, int M, int N, int K,
    int lda, int ldb, int ldc, int kchunk, long long cstride,
    const float* __restrict__ bias) {
    __shared__ float As[16][128 + 4];
    __shared__ float Bs[16][128 + 4];

    int k_begin = 0, k_end = K;
    if (SPLIT) {
        k_begin = blockIdx.z * kchunk;
        k_end = min(K, k_begin + kchunk);
        C += (long long)blockIdx.z * cstride;
    }
    const int bm = blockIdx.y * 128;
    const int bn = blockIdx.x * 128;
    const int tid = threadIdx.x;
    const int tx = tid & 15;
    const int ty = tid >> 4;

    float acc[8][8];
    #pragma unroll
    for (int i = 0; i < 8; i++)
        #pragma unroll
        for (int j = 0; j < 8; j++) acc[i][j] = 0.f;

    for (int k0 = k_begin; k0 < k_end; k0 += 16) {
        #pragma unroll
        for (int s = 0; s < 2; ++s) {
            int idx = tid + s * 256;
            int row = idx >> 2;
            int k4 = (idx & 3) * 4;
            float4 va = *reinterpret_cast<const float4*>(
                &A[(size_t)(bm + row) * lda + k0 + k4]);
            As[k4 + 0][row] = va.x; As[k4 + 1][row] = va.y;
            As[k4 + 2][row] = va.z; As[k4 + 3][row] = va.w;
            float4 vb;
            if (bn + row < N)
                vb = *reinterpret_cast<const float4*>(
                    &B[(size_t)(bn + row) * ldb + k0 + k4]);
            else
                vb = make_float4(0.f, 0.f, 0.f, 0.f);
            Bs[k4 + 0][row] = vb.x; Bs[k4 + 1][row] = vb.y;
            Bs[k4 + 2][row] = vb.z; Bs[k4 + 3][row] = vb.w;
        }
        __syncthreads();
        #pragma unroll
        for (int kk = 0; kk < 16; ++kk) {
            float a[8], b[8];
            *reinterpret_cast<float4*>(&a[0]) =
                *reinterpret_cast<const float4*>(&As[kk][ty * 4]);
            *reinterpret_cast<float4*>(&a[4]) =
                *reinterpret_cast<const float4*>(&As[kk][64 + ty * 4]);
            *reinterpret_cast<float4*>(&b[0]) =
                *reinterpret_cast<const float4*>(&Bs[kk][tx * 4]);
            *reinterpret_cast<float4*>(&b[4]) =
                *reinterpret_cast<const float4*>(&Bs[kk][64 + tx * 4]);
            #pragma unroll
            for (int i = 0; i < 8; i++)
                #pragma unroll
                for (int j = 0; j < 8; j++)
                    acc[i][j] = fmaf(a[i], b[j], acc[i][j]);
        }
        __syncthreads();
    }

    #pragma unroll
    for (int i = 0; i < 8; i++) {
        int ri = bm + ((i < 4) ? (ty * 4 + i) : (64 + ty * 4 + (i - 4)));
        #pragma unroll
        for (int j = 0; j < 8; j++) {
            int cj = bn + ((j < 4) ? (tx * 4 + j) : (64 + tx * 4 + (j - 4)));
            if (cj < N) {
                size_t off = (size_t)ri * ldc + cj;
                float v = acc[i][j];
                if (SOFTP) {
                    float t = v + bias[cj];
                    v = fmaxf(t, 0.f) + log1pf(expf(-fabsf(t)));
                }
                if (ACC) C[off] += v;
                else     C[off]  = v;
            }
        }
    }
}

__global__ void reduce_split_kernel(const float* __restrict__ part,
                                    float* __restrict__ out,
                                    int n, int nz, long long stride) {
    int i = blockIdx.x * blockDim.x + threadIdx.x;
    if (i < n) {
        float s = 0.f;
        for (int z = 0; z < nz; z++) s += part[(long long)z * stride + i];
        out[i] = s;
    }
}

// --------------------- depthwise causal conv + silu ------------------------
__global__ void conv_silu_kernel(const float* __restrict__ xr,
                                 const float* __restrict__ W,
                                 const float* __restrict__ b,
                                 float* __restrict__ u) {
    int idx = blockIdx.x * blockDim.x + threadIdx.x;
    int d = idx & (DINNER - 1);
    int l = idx >> 11;
    float acc = b[d];
    #pragma unroll
    for (int j = 0; j < DCONV; j++) {
        int t = l - (DCONV - 1) + j;
        if (t >= 0) acc = fmaf(xr[(size_t)t * (2 * DINNER) + d], W[d * DCONV + j], acc);
    }
    u[(size_t)l * DINNER + d] = acc * sigm(acc);
}

// --------------- selective scan with fused silu-gate + split ---------------
#define TCHUNK 64
__global__ __launch_bounds__(256) void scan_kernel(
    const float* __restrict__ delta, const float* __restrict__ u,
    const float* __restrict__ xdbl, const float* __restrict__ xr,
    const float* __restrict__ A_log, const float* __restrict__ Dp,
    __half* __restrict__ yh, __half* __restrict__ yl) {
    const int lane_n = threadIdx.x & 15;
    const int ch_loc = threadIdx.x >> 4;
    const int d = blockIdx.x * 16 + ch_loc;
    const float Aneg = -expf(A_log[(size_t)d * DSTATE + lane_n]);
    const float Dval = Dp[d];
    float s = 0.f;

    __shared__ float Bsh[TCHUNK][16];
    __shared__ float Csh[TCHUNK][16];
    __shared__ float dsh[TCHUNK][16];
    __shared__ float ush[TCHUNK][16];

    for (int t0 = 0; t0 < LSEQ; t0 += TCHUNK) {
        __syncthreads();
        for (int i = threadIdx.x; i < TCHUNK * 16; i += 256) {
            int tt = i >> 4, n = i & 15;
            size_t trow = (size_t)(t0 + tt);
            Bsh[tt][n] = xdbl[trow * XDBL_W + DTRANK + n];
            Csh[tt][n] = xdbl[trow * XDBL_W + DTRANK + DSTATE + n];
            dsh[tt][n] = delta[trow * DINNER + blockIdx.x * 16 + n];
            ush[tt][n] = u    [trow * DINNER + blockIdx.x * 16 + n];
        }
        __syncthreads();
        #pragma unroll 4
        for (int tt = 0; tt < TCHUNK; ++tt) {
            float dt = dsh[tt][ch_loc];
            float uu = ush[tt][ch_loc];
            float dA = __expf(dt * Aneg);
            float dBu = dt * uu * Bsh[tt][lane_n];
            s = fmaf(dA, s, dBu);
            float yv = s * Csh[tt][lane_n];
            yv += __shfl_xor_sync(0xffffffffu, yv, 8);
            yv += __shfl_xor_sync(0xffffffffu, yv, 4);
            yv += __shfl_xor_sync(0xffffffffu, yv, 2);
            yv += __shfl_xor_sync(0xffffffffu, yv, 1);
            if (lane_n == 0) {
                size_t trow = (size_t)(t0 + tt);
                float g = yv + Dval * uu;
                float r = xr[trow * (2 * DINNER) + DINNER + d];
                g *= r * sigm(r);
                __half gh = __float2half_rn(g);
                yh[trow * DINNER + d] = gh;
                yl[trow * DINNER + d] = __float2half_rn(g - __half2float(gh));
            }
        }
    }
}

// ------------------------------- launcher ----------------------------------
extern "C" void kernel_launch(void* const* d_in, const int* in_sizes, int n_in,
                              void* d_out, int out_size) {
    const int*   tokens    = (const int*)  d_in[0];
    const float* emb_W     = (const float*)d_in[1];
    const float* in_proj_W = (const float*)d_in[2];
    const float* conv_W    = (const float*)d_in[3];
    const float* conv_b    = (const float*)d_in[4];
    const float* xproj_W   = (const float*)d_in[5];
    const float* dt_W      = (const float*)d_in[6];
    const float* dt_b      = (const float*)d_in[7];
    const float* A_log     = (const float*)d_in[8];
    const float* Dp        = (const float*)d_in[9];
    const float* out_W     = (const float*)d_in[10];
    const float* rms_w     = (const float*)d_in[11];
    const float* rms_b     = (const float*)d_in[12];
    const float* normf_w   = (const float*)d_in[13];
    const float* normf_b   = (const float*)d_in[14];
    float* out = (float*)d_out;

    float *px, *pxr, *pu, *pxdbl, *pdelta, *ppart;
    __half *phh, *phl, *pyh, *pyl, *pwi, *pwo, *pembh;
    cudaGetSymbolAddress((void**)&px,     g_x);
    cudaGetSymbolAddress((void**)&pxr,    g_xr);
    cudaGetSymbolAddress((void**)&pu,     g_u);
    cudaGetSymbolAddress((void**)&pxdbl,  g_xdbl);
    cudaGetSymbolAddress((void**)&pdelta, g_delta);
    cudaGetSymbolAddress((void**)&ppart,  g_part);
    cudaGetSymbolAddress((void**)&phh,    g_hh);
    cudaGetSymbolAddress((void**)&phl,    g_hl);
    cudaGetSymbolAddress((void**)&pyh,    g_yh);
    cudaGetSymbolAddress((void**)&pyl,    g_yl);
    cudaGetSymbolAddress((void**)&pwi,    g_wi);
    cudaGetSymbolAddress((void**)&pwo,    g_wo);
    cudaGetSymbolAddress((void**)&pembh,  g_embh);

    cudaFuncSetAttribute(gemm_fused<false>,
        cudaFuncAttributeMaxDynamicSharedMemorySize, SMEM_G);
    cudaFuncSetAttribute(gemm_fused<true>,
        cudaFuncAttributeMaxDynamicSharedMemorySize, SMEM_G);
    cudaFuncSetAttribute(gemm_mma4,
        cudaFuncAttributeMaxDynamicSharedMemorySize, SMEM_G);

    // ---- weight conversions to fp16 (every launch; deterministic) ----
    {
        int n4 = NLAYERS * 2 * DINNER * NEMBD / 4;
        convert_half_kernel<<<(n4 + 255) / 256, 256>>>(in_proj_W, pwi, n4);
        n4 = NLAYERS * NEMBD * DINNER / 4;
        convert_half_kernel<<<(n4 + 255) / 256, 256>>>(out_W, pwo, n4);
        n4 = (int)((size_t)NVOCAB * NEMBD / 4);
        convert_half_kernel<<<(n4 + 255) / 256, 256>>>(emb_W, pembh, n4);
    }

    embed_kernel<<<LSEQ, 256>>>(tokens, emb_W, px);

    for (int i = 0; i < NLAYERS; i++) {
        rmsnorm_out_kernel<0><<<LSEQ, 256>>>(px, rms_w + i * NEMBD,
                                             rms_b + i * NEMBD, phh, phl);

        // in_proj: xr[L,4096] = h @ W^T  (fused fp16 hi/lo)
        {
            const uint16_t* bw = (const uint16_t*)(pwi + (size_t)i * 2 * DINNER * NEMBD);
            dim3 g(LSEQ / 128, 2 * DINNER / 128);
            gemm_fused<false><<<g, 256, SMEM_G>>>(
                (const uint16_t*)phh, (const uint16_t*)phl, bw,
                pxr, 2 * DINNER, NEMBD, 2 * DINNER);
        }

        conv_silu_kernel<<<LSEQ * DINNER / 256, 256>>>(
            pxr, conv_W + (size_t)i * DINNER * DCONV, conv_b + i * DINNER, pu);

        // x_proj (N=96): split-K fp32
        {
            dim3 grid(1, LSEQ / 128, 8);
            gemm_nt<false, true, false><<<grid, 256>>>(
                pu, xproj_W + (size_t)i * XDBL_W * DINNER, ppart,
                LSEQ, XDBL_W, DINNER, DINNER, DINNER, XDBL_W,
                DINNER / 8, (long long)LSEQ * XDBL_W, nullptr);
            int n = LSEQ * XDBL_W;
            reduce_split_kernel<<<(n + 255) / 256, 256>>>(
                ppart, pxdbl, n, 8, (long long)LSEQ * XDBL_W);
        }

        // dt proj + fused softplus
        {
            dim3 grid(DINNER / 128, LSEQ / 128);
            gemm_nt<false, false, true><<<grid, 256>>>(
                pxdbl, dt_W + (size_t)i * DINNER * DTRANK, pdelta,
                LSEQ, DINNER, DTRANK, XDBL_W, DTRANK, DINNER, 0, 0,
                dt_b + i * DINNER);
        }

        // scan + fused gate + fp16 split
        scan_kernel<<<DINNER / 16, 256>>>(
            pdelta, pu, pxdbl, pxr,
            A_log + (size_t)i * DINNER * DSTATE, Dp + i * DINNER, pyh, pyl);

        // out_proj accumulate: x += y @ out_W^T  (fused fp16 hi/lo)
        {
            const uint16_t* bw = (const uint16_t*)(pwo + (size_t)i * NEMBD * DINNER);
            dim3 g(LSEQ / 128, NEMBD / 128);
            gemm_fused<true><<<g, 256, SMEM_G>>>(
                (const uint16_t*)pyh, (const uint16_t*)pyl, bw,
                px, NEMBD, DINNER, NEMBD);
        }
    }

    // final norm (fp16 out) + tied lm head (fp16 single pass)
    rmsnorm_out_kernel<1><<<LSEQ, 256>>>(px, normf_w, normf_b, phh, nullptr);
    {
        dim3 g(LSEQ / 128, (NVOCAB + 127) / 128);
        gemm_mma4<<<g, 256, SMEM_G>>>(
            (const uint16_t*)phh, (const uint16_t*)pembh,
            out, NVOCAB, NEMBD, NVOCAB);
    }
}